// round 9
// baseline (speedup 1.0000x reference)
#include <cuda_runtime.h>
#include <cuda_bf16.h>

#define N_NODES 50000
#define N_EDGES 800000
#define D_IN    96
#define D_EDGE  32
#define D_OUT   96
#define D_FEAT  128          // D_IN + D_EDGE, matches W's K dimension
#define N_TYPES 4

typedef unsigned long long ull;

#define PACKF2(dst, lo, hi) \
    asm("mov.b64 %0, {%1, %2};" : "=l"(dst) : "f"(lo), "f"(hi))
#define UNPACKF2(lo, hi, src) \
    asm("mov.b64 {%0, %1}, %2;" : "=f"(lo), "=f"(hi) : "l"(src))
// packed dual-FMA: acc.lo += a.lo*b.lo ; acc.hi += a.hi*b.hi
#define FFMA2(acc, a, b) \
    asm("fma.rn.f32x2 %0, %1, %2, %0;" : "+l"(acc) : "l"(a), "l"(b))
// vector global reduction (sm_90+): 16B atomic add
#define REDV4(ptr, v) \
    asm volatile("red.global.add.v4.f32 [%0], {%1, %2, %3, %4};" \
                 :: "l"(ptr), "f"((v).x), "f"((v).y), "f"((v).z), "f"((v).w) \
                 : "memory")

// feat[t][n][0:96]   = sum of x[src] over type-t edges into n
// feat[t][n][96:128] = sum of |ef[src]-ef[dst]| over those edges
// then cnt[t][n] (edge counts as float); +16 pad covers the last tile's
// unguarded cnt pair-reads (up to 15 nodes past N_NODES)
#define FEAT_ELEMS ((size_t)N_TYPES * N_NODES * D_FEAT)
#define CNT_OFFSET FEAT_ELEMS
__device__ float g_scratch[FEAT_ELEMS + (size_t)N_TYPES * N_NODES + 16];

// duplicated, pre-scaled weights/bias for FFMA2 b-operands (L2-resident)
__device__ ull g_wdup[(size_t)N_TYPES * D_FEAT * D_OUT];
__device__ ull g_bdup[(size_t)N_TYPES * D_OUT];

// ---------------------------------------------------------------------------
__global__ __launch_bounds__(256) void prep_kernel(
    const float* __restrict__ W, const float* __restrict__ b)
{
    const int n = N_TYPES * D_FEAT * D_OUT;
    for (int i = blockIdx.x * blockDim.x + threadIdx.x; i < n;
         i += gridDim.x * blockDim.x) {
        float w = 0.25f * W[i];
        ull v; PACKF2(v, w, w);
        g_wdup[i] = v;
    }
    if (blockIdx.x == 0) {
        for (int i = threadIdx.x; i < N_TYPES * D_OUT; i += blockDim.x) {
            float w = 0.25f * b[i];
            ull v; PACKF2(v, w, w);
            g_bdup[i] = v;
        }
    }
}

// ---------------------------------------------------------------------------
// Kernel 1: edge scatter with vector atomics.
// Lane l owns feat bytes [16l, 16l+16): lanes 0-23 carry x[src] (one LDG.128),
// lanes 24-31 carry |ef[s]-ef[d]| (two LDG.128). One red.v4 per lane per edge.
// ---------------------------------------------------------------------------
#define SC_BATCH 4

__global__ __launch_bounds__(256) void scatter_kernel(
    const float* __restrict__ x,      // [N, 96]
    const float* __restrict__ ef,     // [N, 32]
    const int*   __restrict__ src,    // [E]
    const int*   __restrict__ dst,    // [E]
    const int*   __restrict__ et)     // [E]
{
    const int lane = threadIdx.x & 31;
    const int gw   = (blockIdx.x * blockDim.x + threadIdx.x) >> 5;
    const int nw   = (gridDim.x * blockDim.x) >> 5;

    float* cnt = g_scratch + CNT_OFFSET;

    for (long e0 = (long)gw * SC_BATCH; e0 < N_EDGES; e0 += (long)nw * SC_BATCH) {
        int  s[SC_BATCH], d[SC_BATCH], t[SC_BATCH];
        bool v[SC_BATCH];
#pragma unroll
        for (int i = 0; i < SC_BATCH; i++) {
            long e = e0 + i;
            v[i] = (e < N_EDGES);
            long ec = v[i] ? e : 0;
            s[i] = __ldg(&src[ec]);
            d[i] = __ldg(&dst[ec]);
            t[i] = __ldg(&et[ec]);
        }
#pragma unroll
        for (int i = 0; i < SC_BATCH; i++) {
            if (!v[i]) continue;
            float4 val;
            if (lane < 24) {
                val = *reinterpret_cast<const float4*>(
                          x + (size_t)s[i] * D_IN + 4 * lane);
            } else {
                const float4 a = *reinterpret_cast<const float4*>(
                          ef + (size_t)s[i] * D_EDGE + 4 * (lane - 24));
                const float4 b = *reinterpret_cast<const float4*>(
                          ef + (size_t)d[i] * D_EDGE + 4 * (lane - 24));
                val = make_float4(fabsf(a.x - b.x), fabsf(a.y - b.y),
                                  fabsf(a.z - b.z), fabsf(a.w - b.w));
            }
            float* row = g_scratch + ((size_t)t[i] * N_NODES + d[i]) * D_FEAT;
            REDV4(row + 4 * lane, val);
            if (lane == 0)
                atomicAdd(&cnt[(size_t)t[i] * N_NODES + d[i]], 1.0f);
        }
    }
}

// ---------------------------------------------------------------------------
// Kernel 2: out[n] = sum_t ( feat[t][n] @ 0.25*W[t] + cnt[t][n]*0.25*b[t] ).
// smem holds ONLY the transposed feat tile (51.5 KB) -> 3 CTAs/SM, 36 warps.
// W/bias/cnt stream from global (g_wdup L1/L2-hot, pre-duplicated for FFMA2).
// ---------------------------------------------------------------------------
#define TILE_N    96
#define XT_STRIDE 100                         // 400B rows: 16B-aligned
#define SM_XS   (D_FEAT * XT_STRIDE)          // 12800 floats
#define GEMM_SMEM_BYTES (SM_XS * 4)
#define GEMM_THREADS 384

__global__ __launch_bounds__(GEMM_THREADS, 3) void gemm_kernel(
    float* __restrict__ out)          // [N, 96]
{
    extern __shared__ __align__(16) float smem[];
    float (*xs)[XT_STRIDE] = (float(*)[XT_STRIDE])smem;       // [128][100]

    const int node0 = blockIdx.x * TILE_N;
    const int wid   = threadIdx.x >> 5;
    const int lane  = threadIdx.x & 31;
    const int i0    = wid * 8;                // 8 nodes per warp = 4 pairs

    const float* cnt = g_scratch + CNT_OFFSET;

    ull acc[4][3];
#pragma unroll
    for (int p = 0; p < 4; p++)
        acc[p][0] = acc[p][1] = acc[p][2] = 0ull;

    for (int t = 0; t < N_TYPES; t++) {
        __syncthreads();   // previous type's reads done before refill

        // transposed feat tile: coalesced gmem read, strided STS (one-time)
        const float* ft = g_scratch + (size_t)t * N_NODES * D_FEAT;
        for (int i = threadIdx.x; i < TILE_N * D_FEAT; i += GEMM_THREADS) {
            int r = i >> 7, k = i & 127;
            int n = node0 + r;
            xs[k][r] = (n < N_NODES) ? ft[(size_t)n * D_FEAT + k] : 0.0f;
        }
        __syncthreads();

        const ull* Wd = g_wdup + (size_t)t * D_FEAT * D_OUT;

#pragma unroll 8
        for (int k = 0; k < D_FEAT; k++) {
            ull W0 = __ldg(Wd + k * D_OUT + lane);
            ull W1 = __ldg(Wd + k * D_OUT + lane + 32);
            ull W2 = __ldg(Wd + k * D_OUT + lane + 64);
#pragma unroll
            for (int h = 0; h < 2; h++) {
                ulonglong2 xv = *reinterpret_cast<const ulonglong2*>(&xs[k][i0 + 4 * h]);
                FFMA2(acc[2 * h][0],     xv.x, W0);
                FFMA2(acc[2 * h][1],     xv.x, W1);
                FFMA2(acc[2 * h][2],     xv.x, W2);
                FFMA2(acc[2 * h + 1][0], xv.y, W0);
                FFMA2(acc[2 * h + 1][1], xv.y, W1);
                FFMA2(acc[2 * h + 1][2], xv.y, W2);
            }
        }

        // bias: acc[p][c] += pack(cnt_lo, cnt_hi) * pack(b_c, b_c)
        ull B0 = __ldg(&g_bdup[t * D_OUT + lane]);
        ull B1 = __ldg(&g_bdup[t * D_OUT + lane + 32]);
        ull B2 = __ldg(&g_bdup[t * D_OUT + lane + 64]);
        const ull* cp = reinterpret_cast<const ull*>(cnt + (size_t)t * N_NODES + node0);
#pragma unroll
        for (int p = 0; p < 4; p++) {
            ull CN = __ldg(cp + (i0 >> 1) + p);   // (cnt[n_lo], cnt[n_hi])
            FFMA2(acc[p][0], CN, B0);
            FFMA2(acc[p][1], CN, B1);
            FFMA2(acc[p][2], CN, B2);
        }
    }

#pragma unroll
    for (int p = 0; p < 4; p++) {
        int n_lo = node0 + i0 + 2 * p;
        int n_hi = n_lo + 1;
        float* o_lo = out + (size_t)n_lo * D_OUT;
        float* o_hi = out + (size_t)n_hi * D_OUT;
#pragma unroll
        for (int c = 0; c < 3; c++) {
            float lo, hi;
            UNPACKF2(lo, hi, acc[p][c]);
            if (n_lo < N_NODES) o_lo[lane + 32 * c] = lo;
            if (n_hi < N_NODES) o_hi[lane + 32 * c] = hi;
        }
    }
}

// ---------------------------------------------------------------------------
extern "C" void kernel_launch(void* const* d_in, const int* in_sizes, int n_in,
                              void* d_out, int out_size)
{
    const float* x   = (const float*)d_in[0];          // [N, 96]
    const float* ef  = (const float*)d_in[1];          // [N, 32]
    const int*   ei  = (const int*)  d_in[2];          // [2, E]
    const int*   et  = (const int*)  d_in[3];          // [E]
    const float* W   = (const float*)d_in[4];          // [4, 128, 96]
    const float* b   = (const float*)d_in[5];          // [4, 96]
    float*       out = (float*)d_out;                  // [N, 96]

    const int* srcp = ei;
    const int* dstp = ei + N_EDGES;

    // zero the aggregation scratch (feat + cnt)
    void* scratch_ptr = nullptr;
    cudaGetSymbolAddress(&scratch_ptr, g_scratch);
    cudaMemsetAsync(scratch_ptr, 0, sizeof(g_scratch), 0);

    prep_kernel<<<96, 256>>>(W, b);
    scatter_kernel<<<1184, 256>>>(x, ef, srcp, dstp, et);

    static int smem_set = 0;
    if (!smem_set) {
        cudaFuncSetAttribute(gemm_kernel,
                             cudaFuncAttributeMaxDynamicSharedMemorySize,
                             GEMM_SMEM_BYTES);
        smem_set = 1;
    }
    gemm_kernel<<<(N_NODES + TILE_N - 1) / TILE_N, GEMM_THREADS,
                  GEMM_SMEM_BYTES>>>(out);
}

// round 10
// speedup vs baseline: 1.4351x; 1.4351x over previous
#include <cuda_runtime.h>
#include <cuda_bf16.h>

#define N_NODES 50000
#define N_EDGES 800000
#define D_IN    96
#define D_EDGE  32
#define D_OUT   96
#define D_FEAT  128          // D_IN + D_EDGE, matches W's K dimension
#define N_TYPES 4

typedef unsigned long long ull;

#define PACKF2(dst, lo, hi) \
    asm("mov.b64 %0, {%1, %2};" : "=l"(dst) : "f"(lo), "f"(hi))
#define UNPACKF2(lo, hi, src) \
    asm("mov.b64 {%0, %1}, %2;" : "=f"(lo), "=f"(hi) : "l"(src))
// packed dual-FMA: acc.lo += a.lo*b.lo ; acc.hi += a.hi*b.hi
#define FFMA2(acc, a, b) \
    asm("fma.rn.f32x2 %0, %1, %2, %0;" : "+l"(acc) : "l"(a), "l"(b))
// 16B async copy global->shared (overlaps with other fill loads)
#define CPASYNC16(saddr, gptr) \
    asm volatile("cp.async.ca.shared.global [%0], [%1], 16;" \
                 :: "r"(saddr), "l"(gptr) : "memory")
#define CPASYNC_COMMIT() asm volatile("cp.async.commit_group;" ::: "memory")
#define CPASYNC_WAIT0()  asm volatile("cp.async.wait_group 0;" ::: "memory")

// feat[t][n][0:96]   = sum of x[src] over type-t edges into n
// feat[t][n][96:128] = sum of |ef[src]-ef[dst]| over those edges
// then cnt[t][n] (edge counts as float)
#define FEAT_ELEMS ((size_t)N_TYPES * N_NODES * D_FEAT)
#define CNT_OFFSET FEAT_ELEMS
__device__ float g_scratch[FEAT_ELEMS + (size_t)N_TYPES * N_NODES + 16];

// ---------------------------------------------------------------------------
// Kernel 1: edge scatter (R6 scalar-atomic version, measured fastest).
// Per edge: feat[t][dst][lane(+32,+64)] += x[src], [96+lane] += |ef_s-ef_d|,
// cnt[t][dst] += 1. All atomics warp-coalesced 128B rows.
// ---------------------------------------------------------------------------
#define SC_BATCH 4

__global__ __launch_bounds__(256) void scatter_kernel(
    const float* __restrict__ x,      // [N, 96]
    const float* __restrict__ ef,     // [N, 32]
    const int*   __restrict__ src,    // [E]
    const int*   __restrict__ dst,    // [E]
    const int*   __restrict__ et)     // [E]
{
    const int lane = threadIdx.x & 31;
    const int gw   = (blockIdx.x * blockDim.x + threadIdx.x) >> 5;
    const int nw   = (gridDim.x * blockDim.x) >> 5;

    float* cnt = g_scratch + CNT_OFFSET;

    for (long e0 = (long)gw * SC_BATCH; e0 < N_EDGES; e0 += (long)nw * SC_BATCH) {
        int  s[SC_BATCH], d[SC_BATCH], t[SC_BATCH];
        bool v[SC_BATCH];
#pragma unroll
        for (int i = 0; i < SC_BATCH; i++) {
            long e = e0 + i;
            v[i] = (e < N_EDGES);
            long ec = v[i] ? e : 0;
            s[i] = __ldg(&src[ec]);
            d[i] = __ldg(&dst[ec]);
            t[i] = __ldg(&et[ec]);
        }
#pragma unroll
        for (int i = 0; i < SC_BATCH; i++) {
            if (!v[i]) continue;
            const float* xr = x  + (size_t)s[i] * D_IN;
            float x0 = xr[lane], x1 = xr[lane + 32], x2 = xr[lane + 64];
            float ea = ef[(size_t)s[i] * D_EDGE + lane];
            float eb = ef[(size_t)d[i] * D_EDGE + lane];
            float ev = fabsf(ea - eb);

            float* row = g_scratch + ((size_t)t[i] * N_NODES + d[i]) * D_FEAT;
            atomicAdd(row + lane,      x0);
            atomicAdd(row + lane + 32, x1);
            atomicAdd(row + lane + 64, x2);
            atomicAdd(row + lane + 96, ev);
            if (lane == 0)
                atomicAdd(&cnt[(size_t)t[i] * N_NODES + d[i]], 1.0f);
        }
    }
}

// ---------------------------------------------------------------------------
// Kernel 2: out[n] = sum_t ( (0.25*feat[t][n]) @ W[t] + cnt[t][n]*0.25*b[t] ).
// 384 threads, 96-node tiles. The 0.25 is folded into the xs transpose fill,
// so the W tile is a PURE COPY -> loaded with cp.async (overlaps the xs
// fill's DRAM-latency loads). smem ~101 KB -> 2 CTAs/SM.
// ---------------------------------------------------------------------------
#define TILE_N    96
#define XT_STRIDE 100                         // 400B rows: 16B-aligned
#define SM_XS   (D_FEAT * XT_STRIDE)          // 12800 floats
#define SM_W    (D_FEAT * D_OUT)              // 12288 floats
#define GEMM_SMEM_BYTES ((SM_XS + SM_W + D_OUT + TILE_N + 8) * 4)
#define GEMM_THREADS 384

__global__ __launch_bounds__(GEMM_THREADS, 2) void gemm_kernel(
    const float* __restrict__ W,      // [4, 128, 96]
    const float* __restrict__ b,      // [4, 96]
    float*       __restrict__ out)    // [N, 96]
{
    extern __shared__ __align__(16) float smem[];
    float (*xs)[XT_STRIDE] = (float(*)[XT_STRIDE])smem;       // [128][100]
    float* Wsm = smem + SM_XS;                                 // [128*96]
    float* bsm = smem + SM_XS + SM_W;                          // [96]
    float* csm = bsm + D_OUT;                                  // [96]

    const int node0 = blockIdx.x * TILE_N;
    const int wid   = threadIdx.x >> 5;
    const int lane  = threadIdx.x & 31;
    const int i0    = wid * 8;                // 8 nodes per warp = 4 pairs

    const float* cnt = g_scratch + CNT_OFFSET;

    ull acc[4][3];
#pragma unroll
    for (int p = 0; p < 4; p++)
        acc[p][0] = acc[p][1] = acc[p][2] = 0ull;

    for (int t = 0; t < N_TYPES; t++) {
        __syncthreads();   // previous type's reads done before refill

        // W tile: pure async copy (unscaled), 8 x 16B per thread
        {
            const float* Wt = W + (size_t)t * D_FEAT * D_OUT;
            unsigned sw = (unsigned)__cvta_generic_to_shared(Wsm);
#pragma unroll
            for (int j = 0; j < 8; j++) {
                int idx = (j * GEMM_THREADS + threadIdx.x) * 4;   // float index
                CPASYNC16(sw + idx * 4, Wt + idx);
            }
            CPASYNC_COMMIT();
        }
        if (threadIdx.x < D_OUT)
            bsm[threadIdx.x] = 0.25f * b[t * D_OUT + threadIdx.x];
        if (threadIdx.x >= 128 && threadIdx.x < 128 + TILE_N) {
            int r = threadIdx.x - 128;
            int n = node0 + r;
            csm[r] = (n < N_NODES) ? cnt[(size_t)t * N_NODES + n] : 0.0f;
        }
        // transposed feat tile with 0.25 folded in (coalesced gmem reads,
        // strided one-time STS); overlaps the in-flight cp.async W loads
        const float* ft = g_scratch + (size_t)t * N_NODES * D_FEAT;
        for (int i = threadIdx.x; i < TILE_N * D_FEAT; i += GEMM_THREADS) {
            int r = i >> 7, k = i & 127;
            int n = node0 + r;
            xs[k][r] = (n < N_NODES) ? 0.25f * ft[(size_t)n * D_FEAT + k] : 0.0f;
        }
        CPASYNC_WAIT0();
        __syncthreads();

#pragma unroll 8
        for (int k = 0; k < D_FEAT; k++) {
            float w0 = Wsm[k * D_OUT + lane];
            float w1 = Wsm[k * D_OUT + lane + 32];
            float w2 = Wsm[k * D_OUT + lane + 64];
            ull W0, W1, W2;
            PACKF2(W0, w0, w0); PACKF2(W1, w1, w1); PACKF2(W2, w2, w2);
#pragma unroll
            for (int h = 0; h < 2; h++) {
                ulonglong2 xv = *reinterpret_cast<const ulonglong2*>(&xs[k][i0 + 4 * h]);
                FFMA2(acc[2 * h][0],     xv.x, W0);
                FFMA2(acc[2 * h][1],     xv.x, W1);
                FFMA2(acc[2 * h][2],     xv.x, W2);
                FFMA2(acc[2 * h + 1][0], xv.y, W0);
                FFMA2(acc[2 * h + 1][1], xv.y, W1);
                FFMA2(acc[2 * h + 1][2], xv.y, W2);
            }
        }

        // bias: acc[p][c] += pack(cnt_lo, cnt_hi) * pack(0.25 b_c, 0.25 b_c)
        float bb0 = bsm[lane], bb1 = bsm[lane + 32], bb2 = bsm[lane + 64];
        ull B0, B1, B2;
        PACKF2(B0, bb0, bb0); PACKF2(B1, bb1, bb1); PACKF2(B2, bb2, bb2);
#pragma unroll
        for (int p = 0; p < 4; p++) {
            ull CN;
            PACKF2(CN, csm[i0 + 2 * p], csm[i0 + 2 * p + 1]);
            FFMA2(acc[p][0], CN, B0);
            FFMA2(acc[p][1], CN, B1);
            FFMA2(acc[p][2], CN, B2);
        }
    }

#pragma unroll
    for (int p = 0; p < 4; p++) {
        int n_lo = node0 + i0 + 2 * p;
        int n_hi = n_lo + 1;
        float* o_lo = out + (size_t)n_lo * D_OUT;
        float* o_hi = out + (size_t)n_hi * D_OUT;
#pragma unroll
        for (int c = 0; c < 3; c++) {
            float lo, hi;
            UNPACKF2(lo, hi, acc[p][c]);
            if (n_lo < N_NODES) o_lo[lane + 32 * c] = lo;
            if (n_hi < N_NODES) o_hi[lane + 32 * c] = hi;
        }
    }
}

// ---------------------------------------------------------------------------
extern "C" void kernel_launch(void* const* d_in, const int* in_sizes, int n_in,
                              void* d_out, int out_size)
{
    const float* x   = (const float*)d_in[0];          // [N, 96]
    const float* ef  = (const float*)d_in[1];          // [N, 32]
    const int*   ei  = (const int*)  d_in[2];          // [2, E]
    const int*   et  = (const int*)  d_in[3];          // [E]
    const float* W   = (const float*)d_in[4];          // [4, 128, 96]
    const float* b   = (const float*)d_in[5];          // [4, 96]
    float*       out = (float*)d_out;                  // [N, 96]

    const int* srcp = ei;
    const int* dstp = ei + N_EDGES;

    // zero the aggregation scratch (feat + cnt)
    void* scratch_ptr = nullptr;
    cudaGetSymbolAddress(&scratch_ptr, g_scratch);
    cudaMemsetAsync(scratch_ptr, 0, sizeof(g_scratch), 0);

    scatter_kernel<<<592, 256>>>(x, ef, srcp, dstp, et);

    static int smem_set = 0;
    if (!smem_set) {
        cudaFuncSetAttribute(gemm_kernel,
                             cudaFuncAttributeMaxDynamicSharedMemorySize,
                             GEMM_SMEM_BYTES);
        smem_set = 1;
    }
    gemm_kernel<<<(N_NODES + TILE_N - 1) / TILE_N, GEMM_THREADS,
                  GEMM_SMEM_BYTES>>>(W, b, out);
}

// round 11
// speedup vs baseline: 1.4741x; 1.0272x over previous
#include <cuda_runtime.h>
#include <cuda_bf16.h>

#define N_NODES 50000
#define N_EDGES 800000
#define D_IN    96
#define D_EDGE  32
#define D_OUT   96
#define D_FEAT  128          // D_IN + D_EDGE, matches W's K dimension
#define N_TYPES 4

typedef unsigned long long ull;

#define PACKF2(dst, lo, hi) \
    asm("mov.b64 %0, {%1, %2};" : "=l"(dst) : "f"(lo), "f"(hi))
#define UNPACKF2(lo, hi, src) \
    asm("mov.b64 {%0, %1}, %2;" : "=f"(lo), "=f"(hi) : "l"(src))
// packed dual-FMA: acc.lo += a.lo*b.lo ; acc.hi += a.hi*b.hi
#define FFMA2(acc, a, b) \
    asm("fma.rn.f32x2 %0, %1, %2, %0;" : "+l"(acc) : "l"(a), "l"(b))
// 16B async copy global->shared
#define CPASYNC16(saddr, gptr) \
    asm volatile("cp.async.ca.shared.global [%0], [%1], 16;" \
                 :: "r"(saddr), "l"(gptr) : "memory")
#define CPASYNC_COMMIT() asm volatile("cp.async.commit_group;" ::: "memory")
#define CPASYNC_WAIT0()  asm volatile("cp.async.wait_group 0;" ::: "memory")

// feat[t][n][0:96]   = sum of x[src] over type-t edges into n
// feat[t][n][96:128] = sum of |ef[src]-ef[dst]| over those edges
// then cnt[t][n] (edge counts as float)
#define FEAT_ELEMS ((size_t)N_TYPES * N_NODES * D_FEAT)
#define CNT_OFFSET FEAT_ELEMS
__device__ __align__(16) float g_scratch[FEAT_ELEMS + (size_t)N_TYPES * N_NODES + 16];

// ---------------------------------------------------------------------------
// Kernel 1: edge scatter (R6 scalar-atomic version, measured fastest).
// ---------------------------------------------------------------------------
#define SC_BATCH 4

__global__ __launch_bounds__(256) void scatter_kernel(
    const float* __restrict__ x,      // [N, 96]
    const float* __restrict__ ef,     // [N, 32]
    const int*   __restrict__ src,    // [E]
    const int*   __restrict__ dst,    // [E]
    const int*   __restrict__ et)     // [E]
{
    const int lane = threadIdx.x & 31;
    const int gw   = (blockIdx.x * blockDim.x + threadIdx.x) >> 5;
    const int nw   = (gridDim.x * blockDim.x) >> 5;

    float* cnt = g_scratch + CNT_OFFSET;

    for (long e0 = (long)gw * SC_BATCH; e0 < N_EDGES; e0 += (long)nw * SC_BATCH) {
        int  s[SC_BATCH], d[SC_BATCH], t[SC_BATCH];
        bool v[SC_BATCH];
#pragma unroll
        for (int i = 0; i < SC_BATCH; i++) {
            long e = e0 + i;
            v[i] = (e < N_EDGES);
            long ec = v[i] ? e : 0;
            s[i] = __ldg(&src[ec]);
            d[i] = __ldg(&dst[ec]);
            t[i] = __ldg(&et[ec]);
        }
#pragma unroll
        for (int i = 0; i < SC_BATCH; i++) {
            if (!v[i]) continue;
            const float* xr = x  + (size_t)s[i] * D_IN;
            float x0 = xr[lane], x1 = xr[lane + 32], x2 = xr[lane + 64];
            float ea = ef[(size_t)s[i] * D_EDGE + lane];
            float eb = ef[(size_t)d[i] * D_EDGE + lane];
            float ev = fabsf(ea - eb);

            float* row = g_scratch + ((size_t)t[i] * N_NODES + d[i]) * D_FEAT;
            atomicAdd(row + lane,      x0);
            atomicAdd(row + lane + 32, x1);
            atomicAdd(row + lane + 64, x2);
            atomicAdd(row + lane + 96, ev);
            if (lane == 0)
                atomicAdd(&cnt[(size_t)t[i] * N_NODES + d[i]], 1.0f);
        }
    }
}

// ---------------------------------------------------------------------------
// Kernel 2: out[n] = sum_t ( (0.25*feat[t][n]) @ W[t] + cnt[t][n]*0.25*b[t] ).
// 256 threads, TILE_N=64 nodes (8 warps x 8 nodes). xs tile 34.8 KB.
// W streamed per type in double-buffered cp.async chunks of 16 k-rows (12 KB),
// prefetched one chunk ahead (L2-hot). smem ~47.7 KB -> 4 CTAs/SM.
// ---------------------------------------------------------------------------
#define TILE_N    64
#define XT_STRIDE 68                          // 272B rows: 16B-aligned
#define KCHUNK    16
#define NCHUNK    (D_FEAT / KCHUNK)           // 8
#define SM_XS   (D_FEAT * XT_STRIDE)          // 8704 floats
#define SM_WB   (2 * KCHUNK * D_OUT)          // 3072 floats
#define GEMM_SMEM_BYTES ((SM_XS + SM_WB + D_OUT + TILE_N + 8) * 4)
#define GEMM_THREADS 256

__global__ __launch_bounds__(GEMM_THREADS, 4) void gemm_kernel(
    const float* __restrict__ W,      // [4, 128, 96]
    const float* __restrict__ b,      // [4, 96]
    float*       __restrict__ out)    // [N, 96]
{
    extern __shared__ __align__(16) float smem[];
    float (*xs)[XT_STRIDE] = (float(*)[XT_STRIDE])smem;       // [128][68]
    float* wbuf = smem + SM_XS;                                // [2][16][96]
    float* bsm  = smem + SM_XS + SM_WB;                        // [96]
    float* csm  = bsm + D_OUT;                                 // [64]

    const int node0 = blockIdx.x * TILE_N;
    const int tid   = threadIdx.x;
    const int wid   = tid >> 5;
    const int lane  = tid & 31;
    const int i0    = wid * 8;                // 8 nodes per warp = 4 pairs

    const unsigned wb_smem = (unsigned)__cvta_generic_to_shared(wbuf);
    const float* cnt = g_scratch + CNT_OFFSET;

    ull acc[4][3];
#pragma unroll
    for (int p = 0; p < 4; p++)
        acc[p][0] = acc[p][1] = acc[p][2] = 0ull;

    for (int t = 0; t < N_TYPES; t++) {
        __syncthreads();   // previous type's xs/wbuf/bsm reads complete

        const float* Wt = W + (size_t)t * D_FEAT * D_OUT;

        // prefetch W chunk 0 -> wbuf[0]  (384 x 16B, 256 threads)
#pragma unroll
        for (int q = 0; q < 2; q++) {
            int id = q * GEMM_THREADS + tid;
            if (id < KCHUNK * D_OUT / 4)
                CPASYNC16(wb_smem + id * 16, Wt + id * 4);
        }
        CPASYNC_COMMIT();

        // bias / counts
        if (tid < D_OUT)
            bsm[tid] = 0.25f * b[t * D_OUT + tid];
        if (tid >= 128 && tid < 128 + TILE_N) {
            int r = tid - 128;
            int n = node0 + r;
            csm[r] = (n < N_NODES) ? cnt[(size_t)t * N_NODES + n] : 0.0f;
        }

        // transposed feat tile (0.25 folded), float2 gmem reads
        const float* ft = g_scratch + (size_t)t * N_NODES * D_FEAT;
        for (int i2 = tid; i2 < TILE_N * D_FEAT / 2; i2 += GEMM_THREADS) {
            int r  = i2 >> 6;                 // node within tile
            int kp = i2 & 63;                 // k pair
            int n  = node0 + r;
            float2 v = make_float2(0.0f, 0.0f);
            if (n < N_NODES)
                v = *reinterpret_cast<const float2*>(ft + (size_t)n * D_FEAT + 2 * kp);
            xs[2 * kp][r]     = 0.25f * v.x;
            xs[2 * kp + 1][r] = 0.25f * v.y;
        }

        CPASYNC_WAIT0();
        __syncthreads();

        // k-chunk loop: compute chunk j while chunk j+1 streams in
#pragma unroll 1
        for (int j = 0; j < NCHUNK; j++) {
            if (j < NCHUNK - 1) {
                const float* Wc = Wt + (j + 1) * KCHUNK * D_OUT;
                unsigned sb = wb_smem + ((j + 1) & 1) * (KCHUNK * D_OUT * 4);
#pragma unroll
                for (int q = 0; q < 2; q++) {
                    int id = q * GEMM_THREADS + tid;
                    if (id < KCHUNK * D_OUT / 4)
                        CPASYNC16(sb + id * 16, Wc + id * 4);
                }
                CPASYNC_COMMIT();
            }

            const float* wb = wbuf + (j & 1) * (KCHUNK * D_OUT);
#pragma unroll
            for (int kk = 0; kk < KCHUNK; kk++) {
                const int k = j * KCHUNK + kk;
                float w0 = wb[kk * D_OUT + lane];
                float w1 = wb[kk * D_OUT + lane + 32];
                float w2 = wb[kk * D_OUT + lane + 64];
                ull W0, W1, W2;
                PACKF2(W0, w0, w0); PACKF2(W1, w1, w1); PACKF2(W2, w2, w2);
#pragma unroll
                for (int h = 0; h < 2; h++) {
                    ulonglong2 xv = *reinterpret_cast<const ulonglong2*>(
                                        &xs[k][i0 + 4 * h]);
                    FFMA2(acc[2 * h][0],     xv.x, W0);
                    FFMA2(acc[2 * h][1],     xv.x, W1);
                    FFMA2(acc[2 * h][2],     xv.x, W2);
                    FFMA2(acc[2 * h + 1][0], xv.y, W0);
                    FFMA2(acc[2 * h + 1][1], xv.y, W1);
                    FFMA2(acc[2 * h + 1][2], xv.y, W2);
                }
            }

            if (j < NCHUNK - 1) {
                CPASYNC_WAIT0();        // chunk j+1 landed
                __syncthreads();        // nobody still reads buf (j+1)&1
            }
        }

        // bias: acc[p][c] += pack(cnt_lo, cnt_hi) * pack(0.25 b_c, 0.25 b_c)
        float bb0 = bsm[lane], bb1 = bsm[lane + 32], bb2 = bsm[lane + 64];
        ull B0, B1, B2;
        PACKF2(B0, bb0, bb0); PACKF2(B1, bb1, bb1); PACKF2(B2, bb2, bb2);
#pragma unroll
        for (int p = 0; p < 4; p++) {
            ull CN;
            PACKF2(CN, csm[i0 + 2 * p], csm[i0 + 2 * p + 1]);
            FFMA2(acc[p][0], CN, B0);
            FFMA2(acc[p][1], CN, B1);
            FFMA2(acc[p][2], CN, B2);
        }
    }

#pragma unroll
    for (int p = 0; p < 4; p++) {
        int n_lo = node0 + i0 + 2 * p;
        int n_hi = n_lo + 1;
        float* o_lo = out + (size_t)n_lo * D_OUT;
        float* o_hi = out + (size_t)n_hi * D_OUT;
#pragma unroll
        for (int c = 0; c < 3; c++) {
            float lo, hi;
            UNPACKF2(lo, hi, acc[p][c]);
            if (n_lo < N_NODES) o_lo[lane + 32 * c] = lo;
            if (n_hi < N_NODES) o_hi[lane + 32 * c] = hi;
        }
    }
}

// ---------------------------------------------------------------------------
extern "C" void kernel_launch(void* const* d_in, const int* in_sizes, int n_in,
                              void* d_out, int out_size)
{
    const float* x   = (const float*)d_in[0];          // [N, 96]
    const float* ef  = (const float*)d_in[1];          // [N, 32]
    const int*   ei  = (const int*)  d_in[2];          // [2, E]
    const int*   et  = (const int*)  d_in[3];          // [E]
    const float* W   = (const float*)d_in[4];          // [4, 128, 96]
    const float* b   = (const float*)d_in[5];          // [4, 96]
    float*       out = (float*)d_out;                  // [N, 96]

    const int* srcp = ei;
    const int* dstp = ei + N_EDGES;

    // zero the aggregation scratch (feat + cnt)
    void* scratch_ptr = nullptr;
    cudaGetSymbolAddress(&scratch_ptr, g_scratch);
    cudaMemsetAsync(scratch_ptr, 0, sizeof(g_scratch), 0);

    scatter_kernel<<<592, 256>>>(x, ef, srcp, dstp, et);

    static int smem_set = 0;
    if (!smem_set) {
        cudaFuncSetAttribute(gemm_kernel,
                             cudaFuncAttributeMaxDynamicSharedMemorySize,
                             GEMM_SMEM_BYTES);
        smem_set = 1;
    }
    gemm_kernel<<<(N_NODES + TILE_N - 1) / TILE_N, GEMM_THREADS,
                  GEMM_SMEM_BYTES>>>(W, b, out);
}